// round 10
// baseline (speedup 1.0000x reference)
#include <cuda_runtime.h>
#include <cstdint>

#define B 8
#define L 8192
#define C 512
#define NTOK (B * L)           // 65536
#define K_TOP 3687
#define K_RAND 409
#define N_DROP_ROW 4096        // L - keep_len, exact
#define NBINS 4096
#define SEL_THREADS 1024
// dyn smem: hist 16384 + cand 65536 + sel 8192 = 90112
#define SMEM_BYTES (16384 + 65536 + 8192)

// scratch (no allocations allowed)
__device__ float g_norms[NTOK];
__device__ int   g_dropped[NTOK / 2];   // 32768 dropped token ids (global)

// ---------------------------------------------------------------------------
// Kernel 1: token L2 norms + full copy x -> out (measured ~37us, 7.0 TB/s
// aggregate = mixed R/W ceiling). The ONLY kernel that reads x.
// __ldcs: x is never re-read -> evict-first keeps L2 free for the out stream.
// ---------------------------------------------------------------------------
__global__ void norms_copy_kernel(const float4* __restrict__ x,
                                  float4* __restrict__ out) {
    int gt    = blockIdx.x * blockDim.x + threadIdx.x;
    int token = gt >> 4;
    int sub   = gt & 15;
    size_t base = (size_t)token * 128;
    float s = 0.f;
#pragma unroll
    for (int i = 0; i < 8; i++) {
        float4 v = __ldcs(&x[base + sub + i * 16]);
        out[base + sub + i * 16] = v;        // default policy: dirty in L2
        s += v.x * v.x + v.y * v.y + v.z * v.z + v.w * v.w;
    }
#pragma unroll
    for (int o = 8; o; o >>= 1) s += __shfl_xor_sync(0xFFFFFFFFu, s, o, 16);
    if (sub == 0) g_norms[token] = sqrtf(s);
}

// ---------------------------------------------------------------------------
// threefry2x32, JAX-compatible (partitionable, bit_width=32):
// bits[i] = word0 ^ word1 of threefry2x32(key=(0,42), hi=0, lo=i)
// ---------------------------------------------------------------------------
__device__ __forceinline__ uint32_t rotl32(uint32_t x, int d) {
    return (x << d) | (x >> (32 - d));
}

__device__ __forceinline__ uint32_t threefry_xor(uint32_t k1, uint32_t k2,
                                                 uint32_t x0, uint32_t x1) {
    uint32_t ks0 = k1, ks1 = k2, ks2 = k1 ^ k2 ^ 0x1BD11BDAu;
    x0 += ks0; x1 += ks1;
#define TF_R4(a,b,c,d) \
    x0 += x1; x1 = rotl32(x1, a); x1 ^= x0; \
    x0 += x1; x1 = rotl32(x1, b); x1 ^= x0; \
    x0 += x1; x1 = rotl32(x1, c); x1 ^= x0; \
    x0 += x1; x1 = rotl32(x1, d); x1 ^= x0;
    TF_R4(13, 15, 26, 6);  x0 += ks1; x1 += ks2 + 1u;
    TF_R4(17, 29, 16, 24); x0 += ks2; x1 += ks0 + 2u;
    TF_R4(13, 15, 26, 6);  x0 += ks0; x1 += ks1 + 3u;
    TF_R4(17, 29, 16, 24); x0 += ks1; x1 += ks2 + 4u;
    TF_R4(13, 15, 26, 6);  x0 += ks2; x1 += ks0 + 5u;
#undef TF_R4
    return x0 ^ x1;
}

// order-preserving float->uint map
__device__ __forceinline__ unsigned omap(float v) {
    unsigned u = __float_as_uint(v);
    return (u & 0x80000000u) ? ~u : (u | 0x80000000u);
}

// ---------------------------------------------------------------------------
// Exact k-th-largest 64-bit key among 8192 keys
// key(l) = ((u64)um[l] << 32) | (0xFFFFFFFF - l)  (distinct; smaller index
// wins ties — matches jax.lax.top_k). Shift-binning (monotone), suffix scan
// in registers/warp shuffles, exact 64-bit rank-select in the boundary bin.
// ---------------------------------------------------------------------------
__device__ unsigned long long block_select(const unsigned um[8],
                                           unsigned umin, int shift,
                                           unsigned* hist, unsigned long long* cand,
                                           int k, int tid) {
    __shared__ int s_bin, s_need, s_cnt;
    __shared__ unsigned long long s_thr;
    __shared__ unsigned s_wsum[32];
    int lane = tid & 31, wid = tid >> 5;

    if (tid == 0) s_cnt = 0;
    reinterpret_cast<uint4*>(hist)[tid] = make_uint4(0u, 0u, 0u, 0u);
    __syncthreads();

#pragma unroll
    for (int j = 0; j < 8; j++)
        atomicAdd(&hist[(um[j] - umin) >> shift], 1u);
    __syncthreads();

    uint4 c = reinterpret_cast<const uint4*>(hist)[tid];
    unsigned s3 = c.w;
    unsigned s2 = c.z + s3;
    unsigned s1 = c.y + s2;
    unsigned s0 = c.x + s1;
    unsigned tot = s0;

    unsigned inc = tot;
#pragma unroll
    for (int off = 1; off < 32; off <<= 1) {
        unsigned v = __shfl_down_sync(0xFFFFFFFFu, inc, off);
        if (lane < 32 - off) inc += v;
    }
    if (lane == 0) s_wsum[wid] = inc;
    __syncthreads();
    if (wid == 0) {
        unsigned v = s_wsum[lane];
        unsigned inc2 = v;
#pragma unroll
        for (int off = 1; off < 32; off <<= 1) {
            unsigned t = __shfl_down_sync(0xFFFFFFFFu, inc2, off);
            if (lane < 32 - off) inc2 += t;
        }
        s_wsum[lane] = inc2 - v;   // exclusive: count in warps > lane
    }
    __syncthreads();

    unsigned above = s_wsum[wid] + (inc - tot);
    {
        unsigned geq0 = above + s0, abv0 = above + s1;
        unsigned geq1 = above + s1, abv1 = above + s2;
        unsigned geq2 = above + s2, abv2 = above + s3;
        unsigned geq3 = above + s3, abv3 = above;
        unsigned uk = (unsigned)k;
        if (geq0 >= uk && abv0 < uk) { s_bin = 4 * tid + 0; s_need = k - (int)abv0; }
        if (geq1 >= uk && abv1 < uk) { s_bin = 4 * tid + 1; s_need = k - (int)abv1; }
        if (geq2 >= uk && abv2 < uk) { s_bin = 4 * tid + 2; s_need = k - (int)abv2; }
        if (geq3 >= uk && abv3 < uk) { s_bin = 4 * tid + 3; s_need = k - (int)abv3; }
    }
    __syncthreads();

    int bsel = s_bin;
#pragma unroll
    for (int j = 0; j < 8; j++) {
        if ((int)((um[j] - umin) >> shift) == bsel) {
            int p = atomicAdd(&s_cnt, 1);
            int l = tid + j * SEL_THREADS;
            cand[p] = ((unsigned long long)um[j] << 32) | (unsigned)(0xFFFFFFFFu - (unsigned)l);
        }
    }
    __syncthreads();

    int cnt  = s_cnt;
    int need = s_need;
    for (int i = tid; i < cnt; i += SEL_THREADS) {
        unsigned long long ki = cand[i];
        int r = 0;
        for (int j = 0; j < cnt; j++) r += (cand[j] > ki);
        if (r == need - 1) s_thr = ki;
    }
    __syncthreads();
    return s_thr;
}

// ---------------------------------------------------------------------------
// Kernel 2: per-row selection (block = batch row). Emits compact dropped list.
// ---------------------------------------------------------------------------
__global__ void select_kernel() {
    extern __shared__ unsigned char smraw[];
    unsigned*           s_hist = (unsigned*)smraw;                        // 16384 B
    unsigned long long* s_cand = (unsigned long long*)(smraw + 16384);    // 65536 B
    unsigned char*      s_sel  = (unsigned char*)(smraw + 81920);         //  8192 B
    __shared__ unsigned s_minw[32], s_maxw[32];
    __shared__ unsigned s_umin, s_span;
    __shared__ int s_dcnt;

    int row = blockIdx.x;
    int tid = threadIdx.x;
    int lane = tid & 31, wid = tid >> 5;
    const float* norms = &g_norms[row * L];
    if (tid == 0) s_dcnt = 0;

    // ---- pass 1: keys = omap(norm) ----
    unsigned um[8];
    unsigned lmin = 0xFFFFFFFFu, lmax = 0u;
#pragma unroll
    for (int j = 0; j < 8; j++) {
        unsigned u = omap(norms[tid + j * SEL_THREADS]);
        um[j] = u;
        lmin = min(lmin, u);
        lmax = max(lmax, u);
    }
#pragma unroll
    for (int o = 16; o; o >>= 1) {
        lmin = min(lmin, __shfl_xor_sync(0xFFFFFFFFu, lmin, o));
        lmax = max(lmax, __shfl_xor_sync(0xFFFFFFFFu, lmax, o));
    }
    if (lane == 0) { s_minw[wid] = lmin; s_maxw[wid] = lmax; }
    __syncthreads();
    if (wid == 0) {
        unsigned m = s_minw[lane], M = s_maxw[lane];
#pragma unroll
        for (int o = 16; o; o >>= 1) {
            m = min(m, __shfl_xor_sync(0xFFFFFFFFu, m, o));
            M = max(M, __shfl_xor_sync(0xFFFFFFFFu, M, o));
        }
        if (lane == 0) { s_umin = m; s_span = M - m; }
    }
    __syncthreads();
    unsigned umin = s_umin;
    int shift = 20 - __clz(s_span | 1);
    if (shift < 0) shift = 0;

    unsigned long long thr = block_select(um, umin, shift, s_hist, s_cand, K_TOP, tid);
#pragma unroll
    for (int j = 0; j < 8; j++) {
        int l = tid + j * SEL_THREADS;
        unsigned long long key =
            ((unsigned long long)um[j] << 32) | (unsigned)(0xFFFFFFFFu - (unsigned)l);
        s_sel[l] = (key >= thr) ? 1 : 0;
    }
    __syncthreads();

    // ---- pass 2: keys = bits>>9 (strictly monotone in uniform value) ----
#pragma unroll
    for (int j = 0; j < 8; j++) {
        int l = tid + j * SEL_THREADS;
        unsigned bits = threefry_xor(0u, 42u, 0u, (unsigned)(row * L + l));
        um[j] = s_sel[l] ? 0u : (bits >> 9);
    }
    __syncthreads();

    thr = block_select(um, 0u, 11, s_hist, s_cand, K_RAND, tid);
#pragma unroll
    for (int j = 0; j < 8; j++) {
        int l = tid + j * SEL_THREADS;
        unsigned long long key =
            ((unsigned long long)um[j] << 32) | (unsigned)(0xFFFFFFFFu - (unsigned)l);
        int kept = s_sel[l] | ((key >= thr) ? 1 : 0);
        if (!kept) {
            int p = atomicAdd(&s_dcnt, 1);
            g_dropped[row * N_DROP_ROW + p] = row * L + l;
        }
    }
}

// ---------------------------------------------------------------------------
// Kernel 3: zero dropped tokens via the compact list, processed in REVERSE:
// k1 wrote out front-to-back, so the tail of out is still dirty in L2 —
// zeroing it first overwrites dirty lines before their writeback, removing
// doomed DRAM write traffic. 4 tokens per 512-thread block, 1 STG.128/thread.
// ---------------------------------------------------------------------------
__global__ void zero_list_kernel(float4* __restrict__ out) {
    int slot  = blockIdx.x * 4 + (threadIdx.x >> 7);
    int d     = (NTOK / 2 - 1) - slot;               // reversed list order
    int j     = threadIdx.x & 127;
    int token = g_dropped[d];
    out[(size_t)token * 128 + j] = make_float4(0.f, 0.f, 0.f, 0.f);
}

extern "C" void kernel_launch(void* const* d_in, const int* in_sizes, int n_in,
                              void* d_out, int out_size) {
    (void)in_sizes; (void)n_in; (void)out_size;
    const float4* x   = (const float4*)d_in[0];
    float4*       out = (float4*)d_out;

    cudaFuncSetAttribute(select_kernel,
                         cudaFuncAttributeMaxDynamicSharedMemorySize, SMEM_BYTES);

    norms_copy_kernel<<<NTOK * 16 / 256, 256>>>(x, out);
    select_kernel<<<B, SEL_THREADS, SMEM_BYTES>>>();
    zero_list_kernel<<<(NTOK / 2) / 4, 512>>>(out);
}

// round 11
// speedup vs baseline: 1.0659x; 1.0659x over previous
#include <cuda_runtime.h>
#include <cstdint>

#define B 8
#define L 8192
#define C 512
#define NTOK (B * L)           // 65536
#define K_TOP 3687
#define K_RAND 409
#define N_DROP_ROW 4096        // L - keep_len, exact
#define NBINS 4096
#define SEL_THREADS 1024
// dyn smem: hist 16384 + cand 65536 + sel 8192 = 90112
#define SMEM_BYTES (16384 + 65536 + 8192)

// scratch (no allocations allowed)
__device__ float g_norms[NTOK];
__device__ int   g_dropped[NTOK / 2];   // 32768 dropped token ids (global)

// ---------------------------------------------------------------------------
// Kernel 1: token L2 norms + full copy x -> out. Default cache policy on both
// streams (R9 measured 36.8us @ 7.0 TB/s aggregate; __ldcs variant was 4us
// SLOWER — evict-first demotes the read stream). Only kernel reading x.
// ---------------------------------------------------------------------------
__global__ void norms_copy_kernel(const float4* __restrict__ x,
                                  float4* __restrict__ out) {
    int gt    = blockIdx.x * blockDim.x + threadIdx.x;
    int token = gt >> 4;
    int sub   = gt & 15;
    size_t base = (size_t)token * 128;
    float s = 0.f;
#pragma unroll
    for (int i = 0; i < 8; i++) {
        float4 v = x[base + sub + i * 16];
        out[base + sub + i * 16] = v;
        s += v.x * v.x + v.y * v.y + v.z * v.z + v.w * v.w;
    }
#pragma unroll
    for (int o = 8; o; o >>= 1) s += __shfl_xor_sync(0xFFFFFFFFu, s, o, 16);
    if (sub == 0) g_norms[token] = sqrtf(s);
}

// ---------------------------------------------------------------------------
// threefry2x32, JAX-compatible (partitionable, bit_width=32):
// bits[i] = word0 ^ word1 of threefry2x32(key=(0,42), hi=0, lo=i)
// ---------------------------------------------------------------------------
__device__ __forceinline__ uint32_t rotl32(uint32_t x, int d) {
    return (x << d) | (x >> (32 - d));
}

__device__ __forceinline__ uint32_t threefry_xor(uint32_t k1, uint32_t k2,
                                                 uint32_t x0, uint32_t x1) {
    uint32_t ks0 = k1, ks1 = k2, ks2 = k1 ^ k2 ^ 0x1BD11BDAu;
    x0 += ks0; x1 += ks1;
#define TF_R4(a,b,c,d) \
    x0 += x1; x1 = rotl32(x1, a); x1 ^= x0; \
    x0 += x1; x1 = rotl32(x1, b); x1 ^= x0; \
    x0 += x1; x1 = rotl32(x1, c); x1 ^= x0; \
    x0 += x1; x1 = rotl32(x1, d); x1 ^= x0;
    TF_R4(13, 15, 26, 6);  x0 += ks1; x1 += ks2 + 1u;
    TF_R4(17, 29, 16, 24); x0 += ks2; x1 += ks0 + 2u;
    TF_R4(13, 15, 26, 6);  x0 += ks0; x1 += ks1 + 3u;
    TF_R4(17, 29, 16, 24); x0 += ks1; x1 += ks2 + 4u;
    TF_R4(13, 15, 26, 6);  x0 += ks2; x1 += ks0 + 5u;
#undef TF_R4
    return x0 ^ x1;
}

// order-preserving float->uint map
__device__ __forceinline__ unsigned omap(float v) {
    unsigned u = __float_as_uint(v);
    return (u & 0x80000000u) ? ~u : (u | 0x80000000u);
}

// ---------------------------------------------------------------------------
// Exact k-th-largest 64-bit key among 8192 keys
// key(l) = ((u64)um[l] << 32) | (0xFFFFFFFF - l)  (distinct; smaller index
// wins ties — matches jax.lax.top_k). Shift-binning (monotone), suffix scan
// in registers/warp shuffles, exact 64-bit rank-select in the boundary bin.
// ---------------------------------------------------------------------------
__device__ unsigned long long block_select(const unsigned um[8],
                                           unsigned umin, int shift,
                                           unsigned* hist, unsigned long long* cand,
                                           int k, int tid) {
    __shared__ int s_bin, s_need, s_cnt;
    __shared__ unsigned long long s_thr;
    __shared__ unsigned s_wsum[32];
    int lane = tid & 31, wid = tid >> 5;

    if (tid == 0) s_cnt = 0;
    reinterpret_cast<uint4*>(hist)[tid] = make_uint4(0u, 0u, 0u, 0u);
    __syncthreads();

#pragma unroll
    for (int j = 0; j < 8; j++)
        atomicAdd(&hist[(um[j] - umin) >> shift], 1u);
    __syncthreads();

    uint4 c = reinterpret_cast<const uint4*>(hist)[tid];
    unsigned s3 = c.w;
    unsigned s2 = c.z + s3;
    unsigned s1 = c.y + s2;
    unsigned s0 = c.x + s1;
    unsigned tot = s0;

    unsigned inc = tot;
#pragma unroll
    for (int off = 1; off < 32; off <<= 1) {
        unsigned v = __shfl_down_sync(0xFFFFFFFFu, inc, off);
        if (lane < 32 - off) inc += v;
    }
    if (lane == 0) s_wsum[wid] = inc;
    __syncthreads();
    if (wid == 0) {
        unsigned v = s_wsum[lane];
        unsigned inc2 = v;
#pragma unroll
        for (int off = 1; off < 32; off <<= 1) {
            unsigned t = __shfl_down_sync(0xFFFFFFFFu, inc2, off);
            if (lane < 32 - off) inc2 += t;
        }
        s_wsum[lane] = inc2 - v;   // exclusive: count in warps > lane
    }
    __syncthreads();

    unsigned above = s_wsum[wid] + (inc - tot);
    {
        unsigned geq0 = above + s0, abv0 = above + s1;
        unsigned geq1 = above + s1, abv1 = above + s2;
        unsigned geq2 = above + s2, abv2 = above + s3;
        unsigned geq3 = above + s3, abv3 = above;
        unsigned uk = (unsigned)k;
        if (geq0 >= uk && abv0 < uk) { s_bin = 4 * tid + 0; s_need = k - (int)abv0; }
        if (geq1 >= uk && abv1 < uk) { s_bin = 4 * tid + 1; s_need = k - (int)abv1; }
        if (geq2 >= uk && abv2 < uk) { s_bin = 4 * tid + 2; s_need = k - (int)abv2; }
        if (geq3 >= uk && abv3 < uk) { s_bin = 4 * tid + 3; s_need = k - (int)abv3; }
    }
    __syncthreads();

    int bsel = s_bin;
#pragma unroll
    for (int j = 0; j < 8; j++) {
        if ((int)((um[j] - umin) >> shift) == bsel) {
            int p = atomicAdd(&s_cnt, 1);
            int l = tid + j * SEL_THREADS;
            cand[p] = ((unsigned long long)um[j] << 32) | (unsigned)(0xFFFFFFFFu - (unsigned)l);
        }
    }
    __syncthreads();

    int cnt  = s_cnt;
    int need = s_need;
    for (int i = tid; i < cnt; i += SEL_THREADS) {
        unsigned long long ki = cand[i];
        int r = 0;
        for (int j = 0; j < cnt; j++) r += (cand[j] > ki);
        if (r == need - 1) s_thr = ki;
    }
    __syncthreads();
    return s_thr;
}

// ---------------------------------------------------------------------------
// Kernel 2: per-row selection (block = batch row). Emits compact dropped list.
// ---------------------------------------------------------------------------
__global__ void select_kernel() {
    extern __shared__ unsigned char smraw[];
    unsigned*           s_hist = (unsigned*)smraw;                        // 16384 B
    unsigned long long* s_cand = (unsigned long long*)(smraw + 16384);    // 65536 B
    unsigned char*      s_sel  = (unsigned char*)(smraw + 81920);         //  8192 B
    __shared__ unsigned s_minw[32], s_maxw[32];
    __shared__ unsigned s_umin, s_span;
    __shared__ int s_dcnt;

    int row = blockIdx.x;
    int tid = threadIdx.x;
    int lane = tid & 31, wid = tid >> 5;
    const float* norms = &g_norms[row * L];
    if (tid == 0) s_dcnt = 0;

    // ---- pass 1: keys = omap(norm) ----
    unsigned um[8];
    unsigned lmin = 0xFFFFFFFFu, lmax = 0u;
#pragma unroll
    for (int j = 0; j < 8; j++) {
        unsigned u = omap(norms[tid + j * SEL_THREADS]);
        um[j] = u;
        lmin = min(lmin, u);
        lmax = max(lmax, u);
    }
#pragma unroll
    for (int o = 16; o; o >>= 1) {
        lmin = min(lmin, __shfl_xor_sync(0xFFFFFFFFu, lmin, o));
        lmax = max(lmax, __shfl_xor_sync(0xFFFFFFFFu, lmax, o));
    }
    if (lane == 0) { s_minw[wid] = lmin; s_maxw[wid] = lmax; }
    __syncthreads();
    if (wid == 0) {
        unsigned m = s_minw[lane], M = s_maxw[lane];
#pragma unroll
        for (int o = 16; o; o >>= 1) {
            m = min(m, __shfl_xor_sync(0xFFFFFFFFu, m, o));
            M = max(M, __shfl_xor_sync(0xFFFFFFFFu, M, o));
        }
        if (lane == 0) { s_umin = m; s_span = M - m; }
    }
    __syncthreads();
    unsigned umin = s_umin;
    int shift = 20 - __clz(s_span | 1);
    if (shift < 0) shift = 0;

    unsigned long long thr = block_select(um, umin, shift, s_hist, s_cand, K_TOP, tid);
#pragma unroll
    for (int j = 0; j < 8; j++) {
        int l = tid + j * SEL_THREADS;
        unsigned long long key =
            ((unsigned long long)um[j] << 32) | (unsigned)(0xFFFFFFFFu - (unsigned)l);
        s_sel[l] = (key >= thr) ? 1 : 0;
    }
    __syncthreads();

    // ---- pass 2: keys = bits>>9 (strictly monotone in uniform value) ----
#pragma unroll
    for (int j = 0; j < 8; j++) {
        int l = tid + j * SEL_THREADS;
        unsigned bits = threefry_xor(0u, 42u, 0u, (unsigned)(row * L + l));
        um[j] = s_sel[l] ? 0u : (bits >> 9);
    }
    __syncthreads();

    thr = block_select(um, 0u, 11, s_hist, s_cand, K_RAND, tid);
#pragma unroll
    for (int j = 0; j < 8; j++) {
        int l = tid + j * SEL_THREADS;
        unsigned long long key =
            ((unsigned long long)um[j] << 32) | (unsigned)(0xFFFFFFFFu - (unsigned)l);
        int kept = s_sel[l] | ((key >= thr) ? 1 : 0);
        if (!kept) {
            int p = atomicAdd(&s_dcnt, 1);
            g_dropped[row * N_DROP_ROW + p] = row * L + l;
        }
    }
}

// ---------------------------------------------------------------------------
// Kernel 3: zero dropped tokens via compact list, REVERSED order (overwrite
// the still-dirty L2 tail from k1 before writeback — measured ~2.7us win).
// 4 tokens per 512-thread block, 1 STG.128 per thread.
// ---------------------------------------------------------------------------
__global__ void zero_list_kernel(float4* __restrict__ out) {
    int slot  = blockIdx.x * 4 + (threadIdx.x >> 7);
    int d     = (NTOK / 2 - 1) - slot;               // reversed list order
    int j     = threadIdx.x & 127;
    int token = g_dropped[d];
    out[(size_t)token * 128 + j] = make_float4(0.f, 0.f, 0.f, 0.f);
}

extern "C" void kernel_launch(void* const* d_in, const int* in_sizes, int n_in,
                              void* d_out, int out_size) {
    (void)in_sizes; (void)n_in; (void)out_size;
    const float4* x   = (const float4*)d_in[0];
    float4*       out = (float4*)d_out;

    cudaFuncSetAttribute(select_kernel,
                         cudaFuncAttributeMaxDynamicSharedMemorySize, SMEM_BYTES);

    norms_copy_kernel<<<NTOK * 16 / 256, 256>>>(x, out);
    select_kernel<<<B, SEL_THREADS, SMEM_BYTES>>>();
    zero_list_kernel<<<(NTOK / 2) / 4, 512>>>(out);
}

// round 12
// speedup vs baseline: 1.0703x; 1.0041x over previous
#include <cuda_runtime.h>
#include <cstdint>

#define B 8
#define L 8192
#define C 512
#define NTOK (B * L)           // 65536
#define K_TOP 3687
#define K_RAND 409
#define N_DROP_ROW 4096        // L - keep_len, exact
#define NBINS 4096
#define SEL_THREADS 1024
// dyn smem: hist 16384 + cand 65536 + sel 8192 = 90112
#define SMEM_BYTES (16384 + 65536 + 8192)

// scratch (no allocations allowed)
__device__ float g_norms[NTOK];
__device__ int   g_dropped[NTOK / 2];   // 32768 dropped token ids (global)

// ---------------------------------------------------------------------------
// Kernel 1: token L2 norms + full copy x -> out. Default cache policy on both
// streams (measured 37us @ 7.0 TB/s aggregate = mixed R/W ceiling; __ldcs on
// the read stream was 4us SLOWER). The ONLY kernel that reads x.
// ---------------------------------------------------------------------------
__global__ void norms_copy_kernel(const float4* __restrict__ x,
                                  float4* __restrict__ out) {
    int gt    = blockIdx.x * blockDim.x + threadIdx.x;
    int token = gt >> 4;
    int sub   = gt & 15;
    size_t base = (size_t)token * 128;
    float s = 0.f;
#pragma unroll
    for (int i = 0; i < 8; i++) {
        float4 v = x[base + sub + i * 16];
        out[base + sub + i * 16] = v;
        s += v.x * v.x + v.y * v.y + v.z * v.z + v.w * v.w;
    }
#pragma unroll
    for (int o = 8; o; o >>= 1) s += __shfl_xor_sync(0xFFFFFFFFu, s, o, 16);
    if (sub == 0) g_norms[token] = sqrtf(s);
}

// ---------------------------------------------------------------------------
// threefry2x32, JAX-compatible (partitionable, bit_width=32):
// bits[i] = word0 ^ word1 of threefry2x32(key=(0,42), hi=0, lo=i)
// ---------------------------------------------------------------------------
__device__ __forceinline__ uint32_t rotl32(uint32_t x, int d) {
    return (x << d) | (x >> (32 - d));
}

__device__ __forceinline__ uint32_t threefry_xor(uint32_t k1, uint32_t k2,
                                                 uint32_t x0, uint32_t x1) {
    uint32_t ks0 = k1, ks1 = k2, ks2 = k1 ^ k2 ^ 0x1BD11BDAu;
    x0 += ks0; x1 += ks1;
#define TF_R4(a,b,c,d) \
    x0 += x1; x1 = rotl32(x1, a); x1 ^= x0; \
    x0 += x1; x1 = rotl32(x1, b); x1 ^= x0; \
    x0 += x1; x1 = rotl32(x1, c); x1 ^= x0; \
    x0 += x1; x1 = rotl32(x1, d); x1 ^= x0;
    TF_R4(13, 15, 26, 6);  x0 += ks1; x1 += ks2 + 1u;
    TF_R4(17, 29, 16, 24); x0 += ks2; x1 += ks0 + 2u;
    TF_R4(13, 15, 26, 6);  x0 += ks0; x1 += ks1 + 3u;
    TF_R4(17, 29, 16, 24); x0 += ks1; x1 += ks2 + 4u;
    TF_R4(13, 15, 26, 6);  x0 += ks2; x1 += ks0 + 5u;
#undef TF_R4
    return x0 ^ x1;
}

// order-preserving float->uint map
__device__ __forceinline__ unsigned omap(float v) {
    unsigned u = __float_as_uint(v);
    return (u & 0x80000000u) ? ~u : (u | 0x80000000u);
}

// ---------------------------------------------------------------------------
// Exact k-th-largest 64-bit key among 8192 keys
// key(l) = ((u64)um[l] << 32) | (0xFFFFFFFF - l)  (distinct; smaller index
// wins ties — matches jax.lax.top_k). Shift-binning (monotone), suffix scan
// in registers/warp shuffles, exact 64-bit rank-select in the boundary bin.
// ---------------------------------------------------------------------------
__device__ unsigned long long block_select(const unsigned um[8],
                                           unsigned umin, int shift,
                                           unsigned* hist, unsigned long long* cand,
                                           int k, int tid) {
    __shared__ int s_bin, s_need, s_cnt;
    __shared__ unsigned long long s_thr;
    __shared__ unsigned s_wsum[32];
    int lane = tid & 31, wid = tid >> 5;

    if (tid == 0) s_cnt = 0;
    reinterpret_cast<uint4*>(hist)[tid] = make_uint4(0u, 0u, 0u, 0u);
    __syncthreads();

#pragma unroll
    for (int j = 0; j < 8; j++)
        atomicAdd(&hist[(um[j] - umin) >> shift], 1u);
    __syncthreads();

    uint4 c = reinterpret_cast<const uint4*>(hist)[tid];
    unsigned s3 = c.w;
    unsigned s2 = c.z + s3;
    unsigned s1 = c.y + s2;
    unsigned s0 = c.x + s1;
    unsigned tot = s0;

    unsigned inc = tot;
#pragma unroll
    for (int off = 1; off < 32; off <<= 1) {
        unsigned v = __shfl_down_sync(0xFFFFFFFFu, inc, off);
        if (lane < 32 - off) inc += v;
    }
    if (lane == 0) s_wsum[wid] = inc;
    __syncthreads();
    if (wid == 0) {
        unsigned v = s_wsum[lane];
        unsigned inc2 = v;
#pragma unroll
        for (int off = 1; off < 32; off <<= 1) {
            unsigned t = __shfl_down_sync(0xFFFFFFFFu, inc2, off);
            if (lane < 32 - off) inc2 += t;
        }
        s_wsum[lane] = inc2 - v;   // exclusive: count in warps > lane
    }
    __syncthreads();

    unsigned above = s_wsum[wid] + (inc - tot);
    {
        unsigned geq0 = above + s0, abv0 = above + s1;
        unsigned geq1 = above + s1, abv1 = above + s2;
        unsigned geq2 = above + s2, abv2 = above + s3;
        unsigned geq3 = above + s3, abv3 = above;
        unsigned uk = (unsigned)k;
        if (geq0 >= uk && abv0 < uk) { s_bin = 4 * tid + 0; s_need = k - (int)abv0; }
        if (geq1 >= uk && abv1 < uk) { s_bin = 4 * tid + 1; s_need = k - (int)abv1; }
        if (geq2 >= uk && abv2 < uk) { s_bin = 4 * tid + 2; s_need = k - (int)abv2; }
        if (geq3 >= uk && abv3 < uk) { s_bin = 4 * tid + 3; s_need = k - (int)abv3; }
    }
    __syncthreads();

    int bsel = s_bin;
#pragma unroll
    for (int j = 0; j < 8; j++) {
        if ((int)((um[j] - umin) >> shift) == bsel) {
            int p = atomicAdd(&s_cnt, 1);
            int l = tid + j * SEL_THREADS;
            cand[p] = ((unsigned long long)um[j] << 32) | (unsigned)(0xFFFFFFFFu - (unsigned)l);
        }
    }
    __syncthreads();

    int cnt  = s_cnt;
    int need = s_need;
    for (int i = tid; i < cnt; i += SEL_THREADS) {
        unsigned long long ki = cand[i];
        int r = 0;
        for (int j = 0; j < cnt; j++) r += (cand[j] > ki);
        if (r == need - 1) s_thr = ki;
    }
    __syncthreads();
    return s_thr;
}

// ---------------------------------------------------------------------------
// Kernel 2: per-row selection (block = batch row). Emits compact dropped list.
// PDL secondary: waits on k1 via cudaGridDependencySynchronize().
// ---------------------------------------------------------------------------
__global__ void select_kernel() {
    extern __shared__ unsigned char smraw[];
    unsigned*           s_hist = (unsigned*)smraw;                        // 16384 B
    unsigned long long* s_cand = (unsigned long long*)(smraw + 16384);    // 65536 B
    unsigned char*      s_sel  = (unsigned char*)(smraw + 81920);         //  8192 B
    __shared__ unsigned s_minw[32], s_maxw[32];
    __shared__ unsigned s_umin, s_span;
    __shared__ int s_dcnt;

    int row = blockIdx.x;
    int tid = threadIdx.x;
    int lane = tid & 31, wid = tid >> 5;
    const float* norms = &g_norms[row * L];
    if (tid == 0) s_dcnt = 0;

    cudaGridDependencySynchronize();   // wait for k1's g_norms

    // ---- pass 1: keys = omap(norm) ----
    unsigned um[8];
    unsigned lmin = 0xFFFFFFFFu, lmax = 0u;
#pragma unroll
    for (int j = 0; j < 8; j++) {
        unsigned u = omap(norms[tid + j * SEL_THREADS]);
        um[j] = u;
        lmin = min(lmin, u);
        lmax = max(lmax, u);
    }
#pragma unroll
    for (int o = 16; o; o >>= 1) {
        lmin = min(lmin, __shfl_xor_sync(0xFFFFFFFFu, lmin, o));
        lmax = max(lmax, __shfl_xor_sync(0xFFFFFFFFu, lmax, o));
    }
    if (lane == 0) { s_minw[wid] = lmin; s_maxw[wid] = lmax; }
    __syncthreads();
    if (wid == 0) {
        unsigned m = s_minw[lane], M = s_maxw[lane];
#pragma unroll
        for (int o = 16; o; o >>= 1) {
            m = min(m, __shfl_xor_sync(0xFFFFFFFFu, m, o));
            M = max(M, __shfl_xor_sync(0xFFFFFFFFu, M, o));
        }
        if (lane == 0) { s_umin = m; s_span = M - m; }
    }
    __syncthreads();
    unsigned umin = s_umin;
    int shift = 20 - __clz(s_span | 1);
    if (shift < 0) shift = 0;

    unsigned long long thr = block_select(um, umin, shift, s_hist, s_cand, K_TOP, tid);
#pragma unroll
    for (int j = 0; j < 8; j++) {
        int l = tid + j * SEL_THREADS;
        unsigned long long key =
            ((unsigned long long)um[j] << 32) | (unsigned)(0xFFFFFFFFu - (unsigned)l);
        s_sel[l] = (key >= thr) ? 1 : 0;
    }
    __syncthreads();

    // ---- pass 2: keys = bits>>9 (strictly monotone in uniform value) ----
#pragma unroll
    for (int j = 0; j < 8; j++) {
        int l = tid + j * SEL_THREADS;
        unsigned bits = threefry_xor(0u, 42u, 0u, (unsigned)(row * L + l));
        um[j] = s_sel[l] ? 0u : (bits >> 9);
    }
    __syncthreads();

    thr = block_select(um, 0u, 11, s_hist, s_cand, K_RAND, tid);
#pragma unroll
    for (int j = 0; j < 8; j++) {
        int l = tid + j * SEL_THREADS;
        unsigned long long key =
            ((unsigned long long)um[j] << 32) | (unsigned)(0xFFFFFFFFu - (unsigned)l);
        int kept = s_sel[l] | ((key >= thr) ? 1 : 0);
        if (!kept) {
            int p = atomicAdd(&s_dcnt, 1);
            g_dropped[row * N_DROP_ROW + p] = row * L + l;
        }
    }
}

// ---------------------------------------------------------------------------
// Kernel 3: zero dropped tokens via compact list, REVERSED order (overwrite
// the still-dirty L2 tail from k1 before writeback — measured ~2.7us win).
// 8 tokens per 1024-thread block, 1 STG.128 per thread.
// PDL secondary: waits on k2 via cudaGridDependencySynchronize().
// ---------------------------------------------------------------------------
__global__ void zero_list_kernel(float4* __restrict__ out) {
    int slot  = blockIdx.x * 8 + (threadIdx.x >> 7);
    int d     = (NTOK / 2 - 1) - slot;               // reversed list order
    int j     = threadIdx.x & 127;
    cudaGridDependencySynchronize();   // wait for k2's g_dropped
    int token = g_dropped[d];
    out[(size_t)token * 128 + j] = make_float4(0.f, 0.f, 0.f, 0.f);
}

extern "C" void kernel_launch(void* const* d_in, const int* in_sizes, int n_in,
                              void* d_out, int out_size) {
    (void)in_sizes; (void)n_in; (void)out_size;
    const float4* x   = (const float4*)d_in[0];
    float4*       out = (float4*)d_out;

    cudaFuncSetAttribute(select_kernel,
                         cudaFuncAttributeMaxDynamicSharedMemorySize, SMEM_BYTES);

    // k1: plain launch (primary)
    norms_copy_kernel<<<NTOK * 16 / 256, 256>>>(x, out);

    // PDL attribute: allow dependent grid to launch while predecessor runs;
    // correctness enforced by cudaGridDependencySynchronize() in the kernels.
    cudaLaunchAttribute pdl[1];
    pdl[0].id = cudaLaunchAttributeProgrammaticStreamSerialization;
    pdl[0].val.programmaticStreamSerializationAllowed = 1;

    {   // k2
        cudaLaunchConfig_t cfg = {};
        cfg.gridDim = dim3(B, 1, 1);
        cfg.blockDim = dim3(SEL_THREADS, 1, 1);
        cfg.dynamicSmemBytes = SMEM_BYTES;
        cfg.stream = 0;
        cfg.attrs = pdl;
        cfg.numAttrs = 1;
        cudaLaunchKernelEx(&cfg, select_kernel);
    }
    {   // k3
        cudaLaunchConfig_t cfg = {};
        cfg.gridDim = dim3((NTOK / 2) / 8, 1, 1);
        cfg.blockDim = dim3(1024, 1, 1);
        cfg.dynamicSmemBytes = 0;
        cfg.stream = 0;
        cfg.attrs = pdl;
        cfg.numAttrs = 1;
        cudaLaunchKernelEx(&cfg, zero_list_kernel, out);
    }
}